// round 2
// baseline (speedup 1.0000x reference)
#include <cuda_runtime.h>
#include <math.h>

#define D 128
#define NSLOT 8
#define BMAX 65536
#define OUTW 1288   // 2*D + NSLOT*D + NSLOT

// scratch (static device globals; no runtime allocation)
__device__ float g_M[D * D];              // Wq^T Wk
__device__ float g_WfT[D * D];            // Wf^T
__device__ float g_U[(size_t)BMAX * D];   // state @ M
__device__ float g_S[(size_t)BMAX * D];   // softmax-weighted new_slots sum

// ---------------------------------------------------------------------------
// packed fp32x2 helpers (FFMA2 path — ptxas never emits this from C++)
// ---------------------------------------------------------------------------
__device__ __forceinline__ unsigned long long pack2(float x, float y) {
    unsigned long long r;
    asm("mov.b64 %0, {%1, %2};" : "=l"(r) : "f"(x), "f"(y));
    return r;
}
__device__ __forceinline__ void fma2(unsigned long long& d,
                                     unsigned long long a, unsigned long long b) {
    asm("fma.rn.f32x2 %0, %1, %2, %0;" : "+l"(d) : "l"(a), "l"(b));
}
__device__ __forceinline__ float2 unpack2(unsigned long long v) {
    float lo, hi;
    asm("mov.b64 {%0, %1}, %2;" : "=f"(lo), "=f"(hi) : "l"(v));
    return make_float2(lo, hi);
}

// ---------------------------------------------------------------------------
// prep: blocks 0..127 compute M rows, blocks 128..255 transpose Wf
// ---------------------------------------------------------------------------
__global__ void prep_kernel(const float* __restrict__ Wq,
                            const float* __restrict__ Wk,
                            const float* __restrict__ Wf) {
    int d = blockIdx.x;
    int t = threadIdx.x;
    if (d < D) {
        float acc = 0.f;
#pragma unroll 8
        for (int e = 0; e < D; e++)
            acc = fmaf(Wq[e * D + d], Wk[e * D + t], acc);
        g_M[d * D + t] = acc;
    } else {
        int dd = d - D;
        g_WfT[dd * D + t] = Wf[t * D + dd];
    }
}

// ---------------------------------------------------------------------------
// SGEMM with f32x2 packed FMA.
// C[r][c] (+offset coff, row stride ldc) = sum_k A[r][k] * Bm[k][c]
// Block tile: 128 rows x 128 cols, 128 threads, 8 rows x 16 cols per thread.
// As stored transposed [k][row] (stride 132 for conflict-free + aligned LDS.128)
// ---------------------------------------------------------------------------
__global__ __launch_bounds__(128, 2)
void gemm_kernel(const float* __restrict__ A, const float* __restrict__ Bm,
                 float* __restrict__ C, int ldc, int coff) {
    __shared__ float As[32 * 132];
    __shared__ float Bs[32 * 128];

    const int tid = threadIdx.x;
    const int tx = tid & 7;       // col group: cols tx*16 .. tx*16+15
    const int ty = tid >> 3;      // row group: rows ty*8 .. ty*8+7
    const int brow = blockIdx.x * 128;

    unsigned long long acc[8][8];
#pragma unroll
    for (int i = 0; i < 8; i++)
#pragma unroll
        for (int p = 0; p < 8; p++) acc[i][p] = 0ULL;

    const float* arow = A + (size_t)(brow + tid) * D;

    for (int k0 = 0; k0 < D; k0 += 32) {
        __syncthreads();
        // stage A transposed: thread tid owns block-local row tid
#pragma unroll
        for (int j = 0; j < 8; j++) {
            float4 v = *(const float4*)(arow + k0 + 4 * j);
            As[(4 * j + 0) * 132 + tid] = v.x;
            As[(4 * j + 1) * 132 + tid] = v.y;
            As[(4 * j + 2) * 132 + tid] = v.z;
            As[(4 * j + 3) * 132 + tid] = v.w;
        }
        // stage B: 32 x 128, coalesced float4
#pragma unroll
        for (int j = 0; j < 8; j++) {
            int idx = tid + 128 * j;          // 0..1023 float4 indices
            int kr = idx >> 5;                // 0..31
            int c4 = idx & 31;                // 0..31
            *(float4*)(Bs + kr * 128 + c4 * 4) =
                *(const float4*)(Bm + (size_t)(k0 + kr) * D + c4 * 4);
        }
        __syncthreads();

#pragma unroll 8
        for (int kk = 0; kk < 32; kk++) {
            const float* ap = As + kk * 132 + ty * 8;
            float4 a0 = *(const float4*)ap;
            float4 a1 = *(const float4*)(ap + 4);
            const unsigned long long* bp =
                (const unsigned long long*)(Bs + kk * 128 + tx * 16);
            unsigned long long b0 = bp[0], b1 = bp[1], b2 = bp[2], b3 = bp[3];
            unsigned long long b4 = bp[4], b5 = bp[5], b6 = bp[6], b7 = bp[7];
            float av[8] = {a0.x, a0.y, a0.z, a0.w, a1.x, a1.y, a1.z, a1.w};
#pragma unroll
            for (int i = 0; i < 8; i++) {
                unsigned long long a2 = pack2(av[i], av[i]);
                fma2(acc[i][0], a2, b0);
                fma2(acc[i][1], a2, b1);
                fma2(acc[i][2], a2, b2);
                fma2(acc[i][3], a2, b3);
                fma2(acc[i][4], a2, b4);
                fma2(acc[i][5], a2, b5);
                fma2(acc[i][6], a2, b6);
                fma2(acc[i][7], a2, b7);
            }
        }
    }

#pragma unroll
    for (int i = 0; i < 8; i++) {
        float* crow = C + (size_t)(brow + ty * 8 + i) * ldc + coff + tx * 16;
#pragma unroll
        for (int q = 0; q < 4; q++) {
            float2 lo = unpack2(acc[i][2 * q]);
            float2 hi = unpack2(acc[i][2 * q + 1]);
            *(float4*)(crow + 4 * q) = make_float4(lo.x, lo.y, hi.x, hi.y);
        }
    }
}

// ---------------------------------------------------------------------------
// Elementwise kernel v2: 256 threads = 2 rows/block, 4 warps per row.
// Scalar (MUFU-heavy) phase runs in ONE warp per row, broadcast via smem.
// ---------------------------------------------------------------------------
__global__ __launch_bounds__(256)
void ew_kernel(const float* __restrict__ state, const float* __restrict__ slots,
               const float* __restrict__ acts, const float* __restrict__ Wg_w,
               const float* __restrict__ Wg_b, const float* __restrict__ U,
               float* __restrict__ S, float* __restrict__ out) {
    const int r = threadIdx.x >> 7;           // row within block (0/1)
    const int t = threadIdx.x & 127;          // dim index
    const int b = blockIdx.x * 2 + r;
    const int lane = t & 31;
    const int w = t >> 5;                     // warp within row (0..3)

    __shared__ float st[2][D];
    __shared__ float us[2][D];
    __shared__ float sl[2][NSLOT * D];
    __shared__ float a_sh[2][NSLOT];
    __shared__ float dotu[2][NSLOT], dots[2][NSLOT], nrm[2][NSLOT];
    __shared__ float gpart[2][4];
    __shared__ float stn2[2];
    __shared__ float attn_s[2][NSLOT], swv_s[2][NSLOT];
    __shared__ int wsel[2];

    const float sv = state[(size_t)b * D + t];
    st[r][t] = sv;
    us[r][t] = U[(size_t)b * D + t];
    {
        const float4* slv = (const float4*)(slots + (size_t)b * NSLOT * D);
        float4* dst = (float4*)sl[r];
        dst[t] = slv[t];
        dst[t + 128] = slv[t + 128];
    }
    if (t < NSLOT) a_sh[r][t] = acts[(size_t)b * NSLOT + t];
    __syncthreads();

    // decayed activations
    float na[NSLOT];
#pragma unroll
    for (int n = 0; n < NSLOT; n++) na[n] = a_sh[r][n] * 0.95f;

    // gate partial for dim t
    float wm = 0.f;
#pragma unroll
    for (int n = 0; n < NSLOT; n++) wm = fmaf(na[n], sl[r][n * D + t], wm);
    float gdp = fmaf(sv, Wg_w[t], wm * 0.125f * Wg_w[D + t]);

    // per-warp reductions: warp w owns slots 2w, 2w+1
    const int n0 = 2 * w, n1 = 2 * w + 1;
    float du0 = 0, du1 = 0, ds0 = 0, ds1 = 0, q0 = 0, q1 = 0, sn2 = 0;
#pragma unroll
    for (int i = 0; i < 4; i++) {
        int tt = lane + 32 * i;
        float s2 = st[r][tt], u2 = us[r][tt];
        float x0 = sl[r][n0 * D + tt], x1 = sl[r][n1 * D + tt];
        sn2 = fmaf(s2, s2, sn2);
        du0 = fmaf(u2, x0, du0);  du1 = fmaf(u2, x1, du1);
        ds0 = fmaf(s2, x0, ds0);  ds1 = fmaf(s2, x1, ds1);
        q0  = fmaf(x0, x0, q0);   q1  = fmaf(x1, x1, q1);
    }
#pragma unroll
    for (int o = 16; o; o >>= 1) {
        du0 += __shfl_xor_sync(0xFFFFFFFFu, du0, o);
        du1 += __shfl_xor_sync(0xFFFFFFFFu, du1, o);
        ds0 += __shfl_xor_sync(0xFFFFFFFFu, ds0, o);
        ds1 += __shfl_xor_sync(0xFFFFFFFFu, ds1, o);
        q0  += __shfl_xor_sync(0xFFFFFFFFu, q0, o);
        q1  += __shfl_xor_sync(0xFFFFFFFFu, q1, o);
        sn2 += __shfl_xor_sync(0xFFFFFFFFu, sn2, o);
        gdp += __shfl_xor_sync(0xFFFFFFFFu, gdp, o);
    }
    if (lane == 0) {
        dotu[r][n0] = du0; dotu[r][n1] = du1;
        dots[r][n0] = ds0; dots[r][n1] = ds1;
        nrm[r][n0] = q0;   nrm[r][n1] = q1;
        gpart[r][w] = gdp;
        if (w == 0) stn2[r] = sn2;
    }
    __syncthreads();

    // --- scalar phase: one warp per row (lanes redundant; MUFU rt is per-inst) ---
    if (w == 0) {
        const float gd = gpart[r][0] + gpart[r][1] + gpart[r][2] + gpart[r][3] + Wg_b[0];
        const float gate = 1.f / (1.f + __expf(-gd));
        const float stn = fmaxf(sqrtf(stn2[r]), 1e-12f);

        const float inv_sqrt_d = 0.08838834764831845f;  // 1/sqrt(128)
        float attn[NSLOT];
        float mx = -INFINITY;
#pragma unroll
        for (int n = 0; n < NSLOT; n++) {
            attn[n] = dotu[r][n] * inv_sqrt_d * a_sh[r][n];
            mx = fmaxf(mx, attn[n]);
        }
        float se = 0.f;
#pragma unroll
        for (int n = 0; n < NSLOT; n++) {
            attn[n] = __expf(attn[n] - mx);
            se += attn[n];
        }
        const float inv_se = 1.f / se;

        float simmax = -INFINITY;
#pragma unroll
        for (int n = 0; n < NSLOT; n++) {
            float m = (na[n] > 0.01f) ? 1.f : 0.f;
            float c = dots[r][n] / (stn * fmaxf(sqrtf(nrm[r][n]), 1e-12f));
            simmax = fmaxf(simmax, c * m);
        }
        const float novelty = 1.f - fminf(fmaxf(simmax, 0.f), 1.f);
        const bool do_write = (novelty > 0.3f) || (gate > 0.5f);

        int weakest = 0;
        float mn = na[0];
#pragma unroll
        for (int n = 1; n < NSLOT; n++)
            if (na[n] < mn) { mn = na[n]; weakest = n; }

        float swv[NSLOT];
        float swmx = -INFINITY;
#pragma unroll
        for (int n = 0; n < NSLOT; n++) {
            swv[n] = (do_write && n == weakest) ? 1.f : na[n];
            swmx = fmaxf(swmx, swv[n]);
        }
        float ssum = 0.f;
#pragma unroll
        for (int n = 0; n < NSLOT; n++) {
            swv[n] = __expf(swv[n] - swmx);
            ssum += swv[n];
        }
        const float inv_ss = 1.f / ssum;

        if (lane < NSLOT) {
            attn_s[r][lane] = attn[lane] * inv_se;
            swv_s[r][lane]  = swv[lane] * inv_ss;
        }
        if (lane == 0) wsel[r] = do_write ? weakest : -1;
    }
    __syncthreads();

    // --- outputs ---
    const int sel = wsel[r];
    float* orow = out + (size_t)b * OUTW;
    float ro = 0.f, summed = 0.f;
#pragma unroll
    for (int n = 0; n < NSLOT; n++) {
        float x = sl[r][n * D + t];
        ro = fmaf(attn_s[r][n], x, ro);
        float v = (n == sel) ? sv : x;
        orow[2 * D + n * D + t] = v;                 // new_slots
        summed = fmaf(swv_s[r][n], v, summed);
    }
    orow[t] = ro;                                    // read_out
    S[(size_t)b * D + t] = summed;                   // input to summary GEMM
    if (t < NSLOT) {
        float v = (t == sel) ? 1.f : na[t];
        orow[2 * D + NSLOT * D + t] = v;             // new_acts_out
    }
}

// ---------------------------------------------------------------------------
extern "C" void kernel_launch(void* const* d_in, const int* in_sizes, int n_in,
                              void* d_out, int out_size) {
    const float* state = (const float*)d_in[0];
    const float* slots = (const float*)d_in[1];
    const float* acts  = (const float*)d_in[2];
    const float* Wq    = (const float*)d_in[3];
    const float* Wk    = (const float*)d_in[4];
    const float* Wg_w  = (const float*)d_in[5];
    const float* Wg_b  = (const float*)d_in[6];
    const float* Wf    = (const float*)d_in[7];
    float* out = (float*)d_out;

    const int B = in_sizes[0] / D;

    void *pM, *pWfT, *pU, *pS;
    cudaGetSymbolAddress(&pM, g_M);
    cudaGetSymbolAddress(&pWfT, g_WfT);
    cudaGetSymbolAddress(&pU, g_U);
    cudaGetSymbolAddress(&pS, g_S);

    prep_kernel<<<256, 128>>>(Wq, Wk, Wf);
    gemm_kernel<<<B / 128, 128>>>(state, (const float*)pM, (float*)pU, D, 0);
    ew_kernel<<<B / 2, 256>>>(state, slots, acts, Wg_w, Wg_b,
                              (const float*)pU, (float*)pS, out);
    gemm_kernel<<<B / 128, 128>>>((const float*)pS, (const float*)pWfT, out, OUTW, D);
}

// round 3
// speedup vs baseline: 1.1616x; 1.1616x over previous
#include <cuda_runtime.h>
#include <math.h>

#define D 128
#define NSLOT 8
#define BMAX 65536
#define OUTW 1288   // 2*D + NSLOT*D + NSLOT

// scratch (static device globals; no runtime allocation)
__device__ float g_M[D * D];              // Wq^T Wk
__device__ float g_WfT[D * D];            // Wf^T
__device__ float g_U[(size_t)BMAX * D];   // state @ M
__device__ float g_S[(size_t)BMAX * D];   // softmax-weighted new_slots sum

typedef unsigned long long ull;

// ---------------------------------------------------------------------------
// packed fp32x2 helpers (FFMA2 path — ptxas never emits this from C++)
// ---------------------------------------------------------------------------
__device__ __forceinline__ ull pack2(float x, float y) {
    ull r;
    asm("mov.b64 %0, {%1, %2};" : "=l"(r) : "f"(x), "f"(y));
    return r;
}
__device__ __forceinline__ void fma2(ull& d, ull a, ull b) {
    asm("fma.rn.f32x2 %0, %1, %2, %0;" : "+l"(d) : "l"(a), "l"(b));
}
__device__ __forceinline__ float2 unpack2(ull v) {
    float lo, hi;
    asm("mov.b64 {%0, %1}, %2;" : "=f"(lo), "=f"(hi) : "l"(v));
    return make_float2(lo, hi);
}

// dummy kernel: shifts ncu's -s 5 -c 1 capture window onto ew_kernel
__global__ void dummy_kernel() {}

// ---------------------------------------------------------------------------
// prep: blocks 0..127 compute M rows, blocks 128..255 transpose Wf
// ---------------------------------------------------------------------------
__global__ void prep_kernel(const float* __restrict__ Wq,
                            const float* __restrict__ Wk,
                            const float* __restrict__ Wf) {
    int d = blockIdx.x;
    int t = threadIdx.x;
    if (d < D) {
        float acc = 0.f;
#pragma unroll 8
        for (int e = 0; e < D; e++)
            acc = fmaf(Wq[e * D + d], Wk[e * D + t], acc);
        g_M[d * D + t] = acc;
    } else {
        int dd = d - D;
        g_WfT[dd * D + t] = Wf[t * D + dd];
    }
}

// ---------------------------------------------------------------------------
// SGEMM with f32x2 packed FMA, v2.
// C[r][c] (+offset coff, row stride ldc) = sum_k A[r][k] * Bm[k][c]
// Block tile: 128 rows x 128 cols, 256 threads, 8x8 per thread (acc = 32 u64).
// As stored transposed [k][row], stride 132 (16B-aligned, low conflict).
// ---------------------------------------------------------------------------
__global__ __launch_bounds__(256, 2)
void gemm_kernel(const float* __restrict__ A, const float* __restrict__ Bm,
                 float* __restrict__ C, int ldc, int coff) {
    __shared__ float As[32 * 132];
    __shared__ float Bs[32 * 128];

    const int tid = threadIdx.x;
    const int tx = tid & 15;      // col group: cols tx*8 .. tx*8+7
    const int ty = tid >> 4;      // row group: rows ty*8 .. ty*8+7
    const int brow = blockIdx.x * 128;

    ull acc[8][4];
#pragma unroll
    for (int i = 0; i < 8; i++)
#pragma unroll
        for (int p = 0; p < 4; p++) acc[i][p] = 0ULL;

    for (int k0 = 0; k0 < D; k0 += 32) {
        __syncthreads();
        // stage A transposed: 128 rows x 32 k, 1024 float4 loads over 256 threads
#pragma unroll
        for (int j = 0; j < 4; j++) {
            int idx = tid + j * 256;          // 0..1023
            int r = idx >> 3;                 // 0..127
            int c4 = idx & 7;                 // 0..7
            float4 v = *(const float4*)(A + (size_t)(brow + r) * D + k0 + c4 * 4);
            As[(4 * c4 + 0) * 132 + r] = v.x;
            As[(4 * c4 + 1) * 132 + r] = v.y;
            As[(4 * c4 + 2) * 132 + r] = v.z;
            As[(4 * c4 + 3) * 132 + r] = v.w;
        }
        // stage B: 32 x 128, coalesced float4
#pragma unroll
        for (int j = 0; j < 4; j++) {
            int idx = tid + j * 256;          // 0..1023 float4 indices
            int kr = idx >> 5;                // 0..31
            int c4 = idx & 31;                // 0..31
            *(float4*)(Bs + kr * 128 + c4 * 4) =
                *(const float4*)(Bm + (size_t)(k0 + kr) * D + c4 * 4);
        }
        __syncthreads();

#pragma unroll 4
        for (int kk = 0; kk < 32; kk++) {
            const float* ap = As + kk * 132 + ty * 8;
            float4 a0 = *(const float4*)ap;
            float4 a1 = *(const float4*)(ap + 4);
            const ulonglong2* bp =
                (const ulonglong2*)(Bs + kk * 128 + tx * 8);
            ulonglong2 b01 = bp[0];
            ulonglong2 b23 = bp[1];
            float av[8] = {a0.x, a0.y, a0.z, a0.w, a1.x, a1.y, a1.z, a1.w};
#pragma unroll
            for (int i = 0; i < 8; i++) {
                ull a2 = pack2(av[i], av[i]);
                fma2(acc[i][0], a2, b01.x);
                fma2(acc[i][1], a2, b01.y);
                fma2(acc[i][2], a2, b23.x);
                fma2(acc[i][3], a2, b23.y);
            }
        }
    }

#pragma unroll
    for (int i = 0; i < 8; i++) {
        float* crow = C + (size_t)(brow + ty * 8 + i) * ldc + coff + tx * 8;
#pragma unroll
        for (int q = 0; q < 2; q++) {
            float2 lo = unpack2(acc[i][2 * q]);
            float2 hi = unpack2(acc[i][2 * q + 1]);
            *(float4*)(crow + 4 * q) = make_float4(lo.x, lo.y, hi.x, hi.y);
        }
    }
}

// ---------------------------------------------------------------------------
// Elementwise kernel: 256 threads = 2 rows/block, 4 warps per row.
// Scalar (MUFU-heavy) phase runs in ONE warp per row, broadcast via smem.
// ---------------------------------------------------------------------------
__global__ __launch_bounds__(256)
void ew_kernel(const float* __restrict__ state, const float* __restrict__ slots,
               const float* __restrict__ acts, const float* __restrict__ Wg_w,
               const float* __restrict__ Wg_b, const float* __restrict__ U,
               float* __restrict__ S, float* __restrict__ out) {
    const int r = threadIdx.x >> 7;           // row within block (0/1)
    const int t = threadIdx.x & 127;          // dim index
    const int b = blockIdx.x * 2 + r;
    const int lane = t & 31;
    const int w = t >> 5;                     // warp within row (0..3)

    __shared__ float st[2][D];
    __shared__ float us[2][D];
    __shared__ float sl[2][NSLOT * D];
    __shared__ float a_sh[2][NSLOT];
    __shared__ float dotu[2][NSLOT], dots[2][NSLOT], nrm[2][NSLOT];
    __shared__ float gpart[2][4];
    __shared__ float stn2[2];
    __shared__ float attn_s[2][NSLOT], swv_s[2][NSLOT];
    __shared__ int wsel[2];

    const float sv = state[(size_t)b * D + t];
    st[r][t] = sv;
    us[r][t] = U[(size_t)b * D + t];
    {
        const float4* slv = (const float4*)(slots + (size_t)b * NSLOT * D);
        float4* dst = (float4*)sl[r];
        dst[t] = slv[t];
        dst[t + 128] = slv[t + 128];
    }
    if (t < NSLOT) a_sh[r][t] = acts[(size_t)b * NSLOT + t];
    __syncthreads();

    // decayed activations
    float na[NSLOT];
#pragma unroll
    for (int n = 0; n < NSLOT; n++) na[n] = a_sh[r][n] * 0.95f;

    // gate partial for dim t
    float wm = 0.f;
#pragma unroll
    for (int n = 0; n < NSLOT; n++) wm = fmaf(na[n], sl[r][n * D + t], wm);
    float gdp = fmaf(sv, Wg_w[t], wm * 0.125f * Wg_w[D + t]);

    // per-warp reductions: warp w owns slots 2w, 2w+1
    const int n0 = 2 * w, n1 = 2 * w + 1;
    float du0 = 0, du1 = 0, ds0 = 0, ds1 = 0, q0 = 0, q1 = 0, sn2 = 0;
#pragma unroll
    for (int i = 0; i < 4; i++) {
        int tt = lane + 32 * i;
        float s2 = st[r][tt], u2 = us[r][tt];
        float x0 = sl[r][n0 * D + tt], x1 = sl[r][n1 * D + tt];
        sn2 = fmaf(s2, s2, sn2);
        du0 = fmaf(u2, x0, du0);  du1 = fmaf(u2, x1, du1);
        ds0 = fmaf(s2, x0, ds0);  ds1 = fmaf(s2, x1, ds1);
        q0  = fmaf(x0, x0, q0);   q1  = fmaf(x1, x1, q1);
    }
#pragma unroll
    for (int o = 16; o; o >>= 1) {
        du0 += __shfl_xor_sync(0xFFFFFFFFu, du0, o);
        du1 += __shfl_xor_sync(0xFFFFFFFFu, du1, o);
        ds0 += __shfl_xor_sync(0xFFFFFFFFu, ds0, o);
        ds1 += __shfl_xor_sync(0xFFFFFFFFu, ds1, o);
        q0  += __shfl_xor_sync(0xFFFFFFFFu, q0, o);
        q1  += __shfl_xor_sync(0xFFFFFFFFu, q1, o);
        sn2 += __shfl_xor_sync(0xFFFFFFFFu, sn2, o);
        gdp += __shfl_xor_sync(0xFFFFFFFFu, gdp, o);
    }
    if (lane == 0) {
        dotu[r][n0] = du0; dotu[r][n1] = du1;
        dots[r][n0] = ds0; dots[r][n1] = ds1;
        nrm[r][n0] = q0;   nrm[r][n1] = q1;
        gpart[r][w] = gdp;
        if (w == 0) stn2[r] = sn2;
    }
    __syncthreads();

    // --- scalar phase: one warp per row ---
    if (w == 0) {
        const float gd = gpart[r][0] + gpart[r][1] + gpart[r][2] + gpart[r][3] + Wg_b[0];
        const float gate = 1.f / (1.f + __expf(-gd));
        const float stn = fmaxf(sqrtf(stn2[r]), 1e-12f);

        const float inv_sqrt_d = 0.08838834764831845f;  // 1/sqrt(128)
        float attn[NSLOT];
        float mx = -INFINITY;
#pragma unroll
        for (int n = 0; n < NSLOT; n++) {
            attn[n] = dotu[r][n] * inv_sqrt_d * a_sh[r][n];
            mx = fmaxf(mx, attn[n]);
        }
        float se = 0.f;
#pragma unroll
        for (int n = 0; n < NSLOT; n++) {
            attn[n] = __expf(attn[n] - mx);
            se += attn[n];
        }
        const float inv_se = 1.f / se;

        float simmax = -INFINITY;
#pragma unroll
        for (int n = 0; n < NSLOT; n++) {
            float m = (na[n] > 0.01f) ? 1.f : 0.f;
            float c = dots[r][n] / (stn * fmaxf(sqrtf(nrm[r][n]), 1e-12f));
            simmax = fmaxf(simmax, c * m);
        }
        const float novelty = 1.f - fminf(fmaxf(simmax, 0.f), 1.f);
        const bool do_write = (novelty > 0.3f) || (gate > 0.5f);

        int weakest = 0;
        float mn = na[0];
#pragma unroll
        for (int n = 1; n < NSLOT; n++)
            if (na[n] < mn) { mn = na[n]; weakest = n; }

        float swv[NSLOT];
        float swmx = -INFINITY;
#pragma unroll
        for (int n = 0; n < NSLOT; n++) {
            swv[n] = (do_write && n == weakest) ? 1.f : na[n];
            swmx = fmaxf(swmx, swv[n]);
        }
        float ssum = 0.f;
#pragma unroll
        for (int n = 0; n < NSLOT; n++) {
            swv[n] = __expf(swv[n] - swmx);
            ssum += swv[n];
        }
        const float inv_ss = 1.f / ssum;

        if (lane < NSLOT) {
            attn_s[r][lane] = attn[lane] * inv_se;
            swv_s[r][lane]  = swv[lane] * inv_ss;
        }
        if (lane == 0) wsel[r] = do_write ? weakest : -1;
    }
    __syncthreads();

    // --- outputs ---
    const int sel = wsel[r];
    float* orow = out + (size_t)b * OUTW;
    float ro = 0.f, summed = 0.f;
#pragma unroll
    for (int n = 0; n < NSLOT; n++) {
        float x = sl[r][n * D + t];
        ro = fmaf(attn_s[r][n], x, ro);
        float v = (n == sel) ? sv : x;
        orow[2 * D + n * D + t] = v;                 // new_slots
        summed = fmaf(swv_s[r][n], v, summed);
    }
    orow[t] = ro;                                    // read_out
    S[(size_t)b * D + t] = summed;                   // input to summary GEMM
    if (t < NSLOT) {
        float v = (t == sel) ? 1.f : na[t];
        orow[2 * D + NSLOT * D + t] = v;             // new_acts_out
    }
}

// ---------------------------------------------------------------------------
extern "C" void kernel_launch(void* const* d_in, const int* in_sizes, int n_in,
                              void* d_out, int out_size) {
    const float* state = (const float*)d_in[0];
    const float* slots = (const float*)d_in[1];
    const float* acts  = (const float*)d_in[2];
    const float* Wg_w  = (const float*)d_in[5];
    const float* Wg_b  = (const float*)d_in[6];
    const float* Wq    = (const float*)d_in[3];
    const float* Wk    = (const float*)d_in[4];
    const float* Wf    = (const float*)d_in[7];
    float* out = (float*)d_out;

    const int B = in_sizes[0] / D;

    void *pM, *pWfT, *pU, *pS;
    cudaGetSymbolAddress(&pM, g_M);
    cudaGetSymbolAddress(&pWfT, g_WfT);
    cudaGetSymbolAddress(&pU, g_U);
    cudaGetSymbolAddress(&pS, g_S);

    // 3 dummies shift ncu (-s 5 -c 1) onto ew_kernel (launch #6)
    dummy_kernel<<<1, 32>>>();
    dummy_kernel<<<1, 32>>>();
    dummy_kernel<<<1, 32>>>();
    prep_kernel<<<256, 128>>>(Wq, Wk, Wf);
    gemm_kernel<<<B / 128, 256>>>(state, (const float*)pM, (float*)pU, D, 0);
    ew_kernel<<<B / 2, 256>>>(state, slots, acts, Wg_w, Wg_b,
                              (const float*)pU, (float*)pS, out);
    gemm_kernel<<<B / 128, 256>>>((const float*)pS, (const float*)pWfT, out, OUTW, D);
}

// round 4
// speedup vs baseline: 1.5770x; 1.3576x over previous
#include <cuda_runtime.h>
#include <math.h>

#define D 128
#define NSLOT 8
#define BMAX 65536
#define OUTW 1288   // 2*D + NSLOT*D + NSLOT

// scratch (static device globals; no runtime allocation)
__device__ float g_M[D * D];              // Wq^T Wk
__device__ float g_WfT[D * D];            // Wf^T
__device__ float g_U[(size_t)BMAX * D];   // state @ M
__device__ float g_S[(size_t)BMAX * D];   // softmax-weighted new_slots sum

// dummy kernel: shifts ncu capture (launch index 3) onto ew_kernel
__global__ void dummy_kernel() {}

__device__ __forceinline__ float dot4(float4 a, float4 b) {
    return fmaf(a.x, b.x, fmaf(a.y, b.y, fmaf(a.z, b.z, a.w * b.w)));
}

// ---------------------------------------------------------------------------
// prep: blocks 0..127 compute M rows (4 indep accumulators), 128..255 Wf^T
// ---------------------------------------------------------------------------
__global__ void prep_kernel(const float* __restrict__ Wq,
                            const float* __restrict__ Wk,
                            const float* __restrict__ Wf) {
    int d = blockIdx.x;
    int t = threadIdx.x;
    if (d < D) {
        float a0 = 0.f, a1 = 0.f, a2 = 0.f, a3 = 0.f;
#pragma unroll 8
        for (int e = 0; e < D; e += 4) {
            a0 = fmaf(Wq[(e + 0) * D + d], Wk[(e + 0) * D + t], a0);
            a1 = fmaf(Wq[(e + 1) * D + d], Wk[(e + 1) * D + t], a1);
            a2 = fmaf(Wq[(e + 2) * D + d], Wk[(e + 2) * D + t], a2);
            a3 = fmaf(Wq[(e + 3) * D + d], Wk[(e + 3) * D + t], a3);
        }
        g_M[d * D + t] = (a0 + a1) + (a2 + a3);
    } else {
        int dd = d - D;
        g_WfT[dd * D + t] = Wf[t * D + dd];
    }
}

// ---------------------------------------------------------------------------
// SGEMM (R1 version — measured at the FFMA issue ceiling, 59.4us)
// C[r][c] (+offset coff, row stride ldc) = sum_k A[r][k] * Bm[k][c]
// Block tile: 64 rows x 128 cols, 256 threads, 8x4 per thread.
// ---------------------------------------------------------------------------
__global__ __launch_bounds__(256, 2)
void gemm_kernel(const float* __restrict__ A, const float* __restrict__ Bm,
                 float* __restrict__ C, int ldc, int coff) {
    __shared__ float As[64 * 32];
    __shared__ float Bs[32 * D];

    const int tid = threadIdx.x;
    const int tx = tid & 31;      // col group: cols tx*4 .. tx*4+3
    const int ty = tid >> 5;      // row group: rows ty*8 .. ty*8+7
    const int brow = blockIdx.x * 64;

    float acc[8][4];
#pragma unroll
    for (int i = 0; i < 8; i++)
#pragma unroll
        for (int j = 0; j < 4; j++) acc[i][j] = 0.f;

    for (int k0 = 0; k0 < D; k0 += 32) {
#pragma unroll
        for (int j = 0; j < 2; j++) {
            int idx = tid + j * 256;
            int r = idx >> 3;
            int c4 = idx & 7;
            float4 v = *(const float4*)(A + (size_t)(brow + r) * D + k0 + c4 * 4);
            *(float4*)(As + r * 32 + c4 * 4) = v;
        }
#pragma unroll
        for (int j = 0; j < 4; j++) {
            int idx = tid + j * 256;
            int kr = idx >> 5;
            int c4 = idx & 31;
            *(float4*)(Bs + kr * D + c4 * 4) =
                *(const float4*)(Bm + (size_t)(k0 + kr) * D + c4 * 4);
        }
        __syncthreads();

#pragma unroll
        for (int k = 0; k < 32; k += 4) {
            float4 b0 = *(const float4*)(Bs + (k + 0) * D + tx * 4);
            float4 b1 = *(const float4*)(Bs + (k + 1) * D + tx * 4);
            float4 b2 = *(const float4*)(Bs + (k + 2) * D + tx * 4);
            float4 b3 = *(const float4*)(Bs + (k + 3) * D + tx * 4);
#pragma unroll
            for (int i = 0; i < 8; i++) {
                float4 a = *(const float4*)(As + (ty * 8 + i) * 32 + k);
                acc[i][0] = fmaf(a.x, b0.x, acc[i][0]);
                acc[i][1] = fmaf(a.x, b0.y, acc[i][1]);
                acc[i][2] = fmaf(a.x, b0.z, acc[i][2]);
                acc[i][3] = fmaf(a.x, b0.w, acc[i][3]);
                acc[i][0] = fmaf(a.y, b1.x, acc[i][0]);
                acc[i][1] = fmaf(a.y, b1.y, acc[i][1]);
                acc[i][2] = fmaf(a.y, b1.z, acc[i][2]);
                acc[i][3] = fmaf(a.y, b1.w, acc[i][3]);
                acc[i][0] = fmaf(a.z, b2.x, acc[i][0]);
                acc[i][1] = fmaf(a.z, b2.y, acc[i][1]);
                acc[i][2] = fmaf(a.z, b2.z, acc[i][2]);
                acc[i][3] = fmaf(a.z, b2.w, acc[i][3]);
                acc[i][0] = fmaf(a.w, b3.x, acc[i][0]);
                acc[i][1] = fmaf(a.w, b3.y, acc[i][1]);
                acc[i][2] = fmaf(a.w, b3.z, acc[i][2]);
                acc[i][3] = fmaf(a.w, b3.w, acc[i][3]);
            }
        }
        __syncthreads();
    }

#pragma unroll
    for (int i = 0; i < 8; i++) {
        float4 v = make_float4(acc[i][0], acc[i][1], acc[i][2], acc[i][3]);
        *(float4*)(C + (size_t)(brow + ty * 8 + i) * ldc + coff + tx * 4) = v;
    }
}

// ---------------------------------------------------------------------------
// Elementwise kernel v3: ONE WARP PER ROW. 256 threads = 8 rows/block.
// No shared memory, no block barriers. Lane l owns dims [4l, 4l+3].
// ---------------------------------------------------------------------------
__global__ __launch_bounds__(256)
void ew_kernel(const float* __restrict__ state, const float* __restrict__ slots,
               const float* __restrict__ acts, const float* __restrict__ Wg_w,
               const float* __restrict__ Wg_b, const float* __restrict__ U,
               float* __restrict__ S, float* __restrict__ out) {
    const int warp = threadIdx.x >> 5;
    const int lane = threadIdx.x & 31;
    const int b = blockIdx.x * 8 + warp;

    // ---- loads (front-batched, high MLP) ----
    const float4 sv = ((const float4*)state)[(size_t)b * 32 + lane];
    const float4 uv = ((const float4*)U)[(size_t)b * 32 + lane];
    float4 sl[NSLOT];
    {
        const float4* slp = (const float4*)slots + (size_t)b * 256;
#pragma unroll
        for (int n = 0; n < NSLOT; n++) sl[n] = slp[n * 32 + lane];
    }
    const float4 aa = ((const float4*)acts)[(size_t)b * 2];
    const float4 ab = ((const float4*)acts)[(size_t)b * 2 + 1];
    const float4 wg0 = ((const float4*)Wg_w)[lane];
    const float4 wg1 = ((const float4*)Wg_w)[32 + lane];

    float a_[NSLOT] = {aa.x, aa.y, aa.z, aa.w, ab.x, ab.y, ab.z, ab.w};
    float na[NSLOT];
#pragma unroll
    for (int n = 0; n < NSLOT; n++) na[n] = a_[n] * 0.95f;

    // ---- per-lane partials ----
    float4 wm4 = make_float4(0.f, 0.f, 0.f, 0.f);
#pragma unroll
    for (int n = 0; n < NSLOT; n++) {
        wm4.x = fmaf(na[n], sl[n].x, wm4.x);
        wm4.y = fmaf(na[n], sl[n].y, wm4.y);
        wm4.z = fmaf(na[n], sl[n].z, wm4.z);
        wm4.w = fmaf(na[n], sl[n].w, wm4.w);
    }
    float gdp = fmaf(0.125f, dot4(wm4, wg1), dot4(sv, wg0));
    float sn2 = dot4(sv, sv);
    float du[NSLOT], ds[NSLOT], qn[NSLOT];
#pragma unroll
    for (int n = 0; n < NSLOT; n++) {
        du[n] = dot4(uv, sl[n]);
        ds[n] = dot4(sv, sl[n]);
        qn[n] = dot4(sl[n], sl[n]);
    }

    // ---- butterfly reductions (26 values, results replicated) ----
#pragma unroll
    for (int o = 16; o; o >>= 1) {
#pragma unroll
        for (int n = 0; n < NSLOT; n++) {
            du[n] += __shfl_xor_sync(0xFFFFFFFFu, du[n], o);
            ds[n] += __shfl_xor_sync(0xFFFFFFFFu, ds[n], o);
            qn[n] += __shfl_xor_sync(0xFFFFFFFFu, qn[n], o);
        }
        sn2 += __shfl_xor_sync(0xFFFFFFFFu, sn2, o);
        gdp += __shfl_xor_sync(0xFFFFFFFFu, gdp, o);
    }

    // ---- scalar phase (redundant per lane) ----
    const float gd = gdp + Wg_b[0];
    const float gate = 1.f / (1.f + __expf(-gd));
    const float stn = fmaxf(sqrtf(sn2), 1e-12f);
    const float inv_stn = 1.f / stn;

    const float inv_sqrt_d = 0.08838834764831845f;  // 1/sqrt(128)
    float attn[NSLOT];
    float mx = -INFINITY;
#pragma unroll
    for (int n = 0; n < NSLOT; n++) {
        attn[n] = du[n] * inv_sqrt_d * a_[n];
        mx = fmaxf(mx, attn[n]);
    }
    float se = 0.f;
#pragma unroll
    for (int n = 0; n < NSLOT; n++) {
        attn[n] = __expf(attn[n] - mx);
        se += attn[n];
    }
    const float inv_se = 1.f / se;

    float simmax = -INFINITY;
#pragma unroll
    for (int n = 0; n < NSLOT; n++) {
        float m = (na[n] > 0.01f) ? 1.f : 0.f;
        float c = ds[n] * inv_stn / fmaxf(sqrtf(qn[n]), 1e-12f);
        simmax = fmaxf(simmax, c * m);
    }
    const float novelty = 1.f - fminf(fmaxf(simmax, 0.f), 1.f);
    const bool do_write = (novelty > 0.3f) || (gate > 0.5f);

    int weakest = 0;
    float mn = na[0];
#pragma unroll
    for (int n = 1; n < NSLOT; n++)
        if (na[n] < mn) { mn = na[n]; weakest = n; }
    const int sel = do_write ? weakest : -1;

    float swv[NSLOT];
    float swmx = -INFINITY;
#pragma unroll
    for (int n = 0; n < NSLOT; n++) {
        swv[n] = (n == sel) ? 1.f : na[n];
        swmx = fmaxf(swmx, swv[n]);
    }
    float ssum = 0.f;
#pragma unroll
    for (int n = 0; n < NSLOT; n++) {
        swv[n] = __expf(swv[n] - swmx);
        ssum += swv[n];
    }
    const float inv_ss = 1.f / ssum;

    // ---- outputs (all float4, row base 5152B = 16B aligned) ----
    float4* orow4 = (float4*)(out + (size_t)b * OUTW);
    float4 ro = make_float4(0.f, 0.f, 0.f, 0.f);
    float4 sm = make_float4(0.f, 0.f, 0.f, 0.f);
#pragma unroll
    for (int n = 0; n < NSLOT; n++) {
        const float wa = attn[n] * inv_se;
        const float ws = swv[n] * inv_ss;
        float4 x = sl[n];
        float4 v = (n == sel) ? sv : x;
        ro.x = fmaf(wa, x.x, ro.x);  ro.y = fmaf(wa, x.y, ro.y);
        ro.z = fmaf(wa, x.z, ro.z);  ro.w = fmaf(wa, x.w, ro.w);
        sm.x = fmaf(ws, v.x, sm.x);  sm.y = fmaf(ws, v.y, sm.y);
        sm.z = fmaf(ws, v.z, sm.z);  sm.w = fmaf(ws, v.w, sm.w);
        orow4[64 + n * 32 + lane] = v;              // new_slots
    }
    orow4[lane] = ro;                               // read_out
    ((float4*)S)[(size_t)b * 32 + lane] = sm;       // summary GEMM input
    if (lane < NSLOT) {
        float v = (lane == sel) ? 1.f : na[lane];
        out[(size_t)b * OUTW + 2 * D + NSLOT * D + lane] = v;  // new_acts_out
    }
}

// ---------------------------------------------------------------------------
extern "C" void kernel_launch(void* const* d_in, const int* in_sizes, int n_in,
                              void* d_out, int out_size) {
    const float* state = (const float*)d_in[0];
    const float* slots = (const float*)d_in[1];
    const float* acts  = (const float*)d_in[2];
    const float* Wq    = (const float*)d_in[3];
    const float* Wk    = (const float*)d_in[4];
    const float* Wg_w  = (const float*)d_in[5];
    const float* Wg_b  = (const float*)d_in[6];
    const float* Wf    = (const float*)d_in[7];
    float* out = (float*)d_out;

    const int B = in_sizes[0] / D;

    void *pM, *pWfT, *pU, *pS;
    cudaGetSymbolAddress(&pM, g_M);
    cudaGetSymbolAddress(&pWfT, g_WfT);
    cudaGetSymbolAddress(&pU, g_U);
    cudaGetSymbolAddress(&pS, g_S);

    // launch index 3 (ew) is what ncu captures
    dummy_kernel<<<1, 32>>>();
    prep_kernel<<<256, 128>>>(Wq, Wk, Wf);
    gemm_kernel<<<B / 64, 256>>>(state, (const float*)pM, (float*)pU, D, 0);
    ew_kernel<<<B / 8, 256>>>(state, slots, acts, Wg_w, Wg_b,
                              (const float*)pU, (float*)pS, out);
    gemm_kernel<<<B / 64, 256>>>((const float*)pS, (const float*)pWfT, out, OUTW, D);
}

// round 6
// speedup vs baseline: 1.8305x; 1.1608x over previous
#include <cuda_runtime.h>
#include <cuda_bf16.h>
#include <math.h>

#define D 128
#define NSLOT 8
#define BMAX 65536
#define OUTW 1288   // 2*D + NSLOT*D + NSLOT

// scratch (static device globals; no runtime allocation)
__device__ float g_U[(size_t)BMAX * D];   // state @ M
__device__ float g_S[(size_t)BMAX * D];   // softmax-weighted new_slots sum
// B operands in per-lane mma fragment layout (uint2 per lane per 16x8 tile)
__device__ uint2 g_BUhi[D * D / 4], g_BUlo[D * D / 4];   // B[k][n] = M[k][n]
__device__ uint2 g_BFhi[D * D / 4], g_BFlo[D * D / 4];   // B[k][n] = Wf[n][k]

// ---------------------------------------------------------------------------
// helpers
// ---------------------------------------------------------------------------
__device__ __forceinline__ float dot4(float4 a, float4 b) {
    return fmaf(a.x, b.x, fmaf(a.y, b.y, fmaf(a.z, b.z, a.w * b.w)));
}
// pack two f32 -> bf16x2 (x -> low half, y -> high half)
__device__ __forceinline__ unsigned pack_bf(float x, float y) {
    unsigned r;
    asm("cvt.rn.bf16x2.f32 %0, %1, %2;" : "=r"(r) : "f"(y), "f"(x));
    return r;
}
__device__ __forceinline__ float lo_f(unsigned r) { return __uint_as_float(r << 16); }
__device__ __forceinline__ float hi_f(unsigned r) { return __uint_as_float(r & 0xffff0000u); }

__device__ __forceinline__ void mma_bf16(float* c, uint4 a, uint2 b) {
    asm volatile(
        "mma.sync.aligned.m16n8k16.row.col.f32.bf16.bf16.f32 "
        "{%0,%1,%2,%3}, {%4,%5,%6,%7}, {%8,%9}, {%0,%1,%2,%3};"
        : "+f"(c[0]), "+f"(c[1]), "+f"(c[2]), "+f"(c[3])
        : "r"(a.x), "r"(a.y), "r"(a.z), "r"(a.w), "r"(b.x), "r"(b.y));
}

// fragment address math for B (16x8 k×n tile), PTX ISA m16n8k16 ownership:
//   lane = (n%8)*4 + (k%8)/2 ; reg = (k%16)/8 ; half = k%2
__device__ __forceinline__ void store_b_frag(uint2* arr, int k, int n,
                                             unsigned short bits) {
    int lane = ((n & 7) << 2) + ((k & 7) >> 1);
    int fs = ((k >> 4) << 4) + (n >> 3);           // frag-set = ktile*16 + ntile
    int us = (fs * 32 + lane) * 4 + (((k >> 3) & 1) << 1) + (k & 1);
    ((unsigned short*)arr)[us] = bits;
}

// ---------------------------------------------------------------------------
// prep: blocks 0..127 compute M[d][*] = (Wq^T Wk)[d][*] -> g_BU (k=d, n=t)
//       blocks 128..255: Wf rows -> g_BF (B[k][n] = Wf[n][k]: n=blk, k=t)
// ---------------------------------------------------------------------------
__global__ void prep_kernel(const float* __restrict__ Wq,
                            const float* __restrict__ Wk,
                            const float* __restrict__ Wf) {
    int d = blockIdx.x;
    int t = threadIdx.x;
    if (d < D) {
        float a0 = 0.f, a1 = 0.f, a2 = 0.f, a3 = 0.f;
#pragma unroll 8
        for (int e = 0; e < D; e += 4) {
            a0 = fmaf(Wq[(e + 0) * D + d], Wk[(e + 0) * D + t], a0);
            a1 = fmaf(Wq[(e + 1) * D + d], Wk[(e + 1) * D + t], a1);
            a2 = fmaf(Wq[(e + 2) * D + d], Wk[(e + 2) * D + t], a2);
            a3 = fmaf(Wq[(e + 3) * D + d], Wk[(e + 3) * D + t], a3);
        }
        float m = (a0 + a1) + (a2 + a3);
        __nv_bfloat16 hb = __float2bfloat16(m);
        float lo = m - __bfloat162float(hb);
        __nv_bfloat16 lb = __float2bfloat16(lo);
        store_b_frag(g_BUhi, d, t, *(unsigned short*)&hb);
        store_b_frag(g_BUlo, d, t, *(unsigned short*)&lb);
    } else {
        int n = d - D;
        float m = Wf[n * D + t];
        __nv_bfloat16 hb = __float2bfloat16(m);
        float lo = m - __bfloat162float(hb);
        __nv_bfloat16 lb = __float2bfloat16(lo);
        store_b_frag(g_BFhi, t, n, *(unsigned short*)&hb);
        store_b_frag(g_BFlo, t, n, *(unsigned short*)&lb);
    }
}

// ---------------------------------------------------------------------------
// Tensor-core GEMM via mma.sync bf16, 3-term split.
// C[brow+m][coff+n] = sum_k A[brow+m][k] * B[k][n]
// 256 threads, 128x128 tile/CTA. A converted fp32->bf16 hi/lo into smem frags.
// B frags LDG'd from global (L1-resident, 64KB shared across CTAs).
// ---------------------------------------------------------------------------
__global__ __launch_bounds__(256)
void tc_gemm(const float* __restrict__ A,
             const uint2* __restrict__ Bhi, const uint2* __restrict__ Blo,
             float* __restrict__ C, int ldc, int coff) {
    extern __shared__ char smem[];
    uint4* sH = (uint4*)smem;              // [kt(8)][mt(8)][lane(32)] A-hi frags
    uint4* sL = (uint4*)(smem + 32768);    // A-lo frags

    const int tid = threadIdx.x;
    const int warp = tid >> 5;             // 0..7
    const int lane = tid & 31;
    const int brow = blockIdx.x * 128;

    // ---- convert phase: warp w owns mtile = w, loops ktiles ----
    {
        const int mt = warp;
        const int r = brow + mt * 16 + (lane >> 2);
        const int cbase = (lane & 3) << 1;
        const float* ap = A + (size_t)r * D + cbase;
#pragma unroll
        for (int kt = 0; kt < 8; kt++) {
            const float* p = ap + kt * 16;
            float2 p00 = *(const float2*)p;
            float2 p01 = *(const float2*)(p + 8);
            float2 p10 = *(const float2*)(p + 8 * D);
            float2 p11 = *(const float2*)(p + 8 * D + 8);
            uint4 h, l;
            h.x = pack_bf(p00.x, p00.y);
            h.y = pack_bf(p10.x, p10.y);
            h.z = pack_bf(p01.x, p01.y);
            h.w = pack_bf(p11.x, p11.y);
            l.x = pack_bf(p00.x - lo_f(h.x), p00.y - hi_f(h.x));
            l.y = pack_bf(p10.x - lo_f(h.y), p10.y - hi_f(h.y));
            l.z = pack_bf(p01.x - lo_f(h.z), p01.y - hi_f(h.z));
            l.w = pack_bf(p11.x - lo_f(h.w), p11.y - hi_f(h.w));
            int idx = (kt * 8 + mt) * 32 + lane;
            sH[idx] = h;
            sL[idx] = l;
        }
    }
    __syncthreads();

    // ---- mma phase: warp computes 32 rows x 64 cols ----
    const int wm = warp & 3;               // m-group: mtiles 2wm, 2wm+1
    const int wn = warp >> 2;              // n-group: ntiles wn*8..+7
    float acc[2][8][4];
#pragma unroll
    for (int i = 0; i < 2; i++)
#pragma unroll
        for (int j = 0; j < 8; j++)
#pragma unroll
            for (int q = 0; q < 4; q++) acc[i][j][q] = 0.f;

#pragma unroll
    for (int kt = 0; kt < 8; kt++) {
        const int m0 = 2 * wm;
        uint4 ah0 = sH[(kt * 8 + m0) * 32 + lane];
        uint4 ah1 = sH[(kt * 8 + m0 + 1) * 32 + lane];
        uint4 al0 = sL[(kt * 8 + m0) * 32 + lane];
        uint4 al1 = sL[(kt * 8 + m0 + 1) * 32 + lane];
#pragma unroll
        for (int nt = 0; nt < 8; nt++) {
            int fs = kt * 16 + wn * 8 + nt;
            uint2 bh = Bhi[fs * 32 + lane];
            uint2 bl = Blo[fs * 32 + lane];
            mma_bf16(acc[0][nt], ah0, bh);
            mma_bf16(acc[1][nt], ah1, bh);
            mma_bf16(acc[0][nt], ah0, bl);
            mma_bf16(acc[1][nt], ah1, bl);
            mma_bf16(acc[0][nt], al0, bh);
            mma_bf16(acc[1][nt], al1, bh);
        }
    }

    // ---- epilogue: c0,c1 -> (row, col..col+1); c2,c3 -> (row+8, ...) ----
#pragma unroll
    for (int i = 0; i < 2; i++) {
        const int row = brow + (2 * wm + i) * 16 + (lane >> 2);
#pragma unroll
        for (int nt = 0; nt < 8; nt++) {
            const int col = coff + wn * 64 + nt * 8 + ((lane & 3) << 1);
            float* cp = C + (size_t)row * ldc + col;
            *(float2*)cp = make_float2(acc[i][nt][0], acc[i][nt][1]);
            *(float2*)(cp + 8 * ldc) = make_float2(acc[i][nt][2], acc[i][nt][3]);
        }
    }
}

// ---------------------------------------------------------------------------
// Elementwise kernel v3 (unchanged — at memory roofline, 122us)
// ---------------------------------------------------------------------------
__global__ __launch_bounds__(256)
void ew_kernel(const float* __restrict__ state, const float* __restrict__ slots,
               const float* __restrict__ acts, const float* __restrict__ Wg_w,
               const float* __restrict__ Wg_b, const float* __restrict__ U,
               float* __restrict__ S, float* __restrict__ out) {
    const int warp = threadIdx.x >> 5;
    const int lane = threadIdx.x & 31;
    const int b = blockIdx.x * 8 + warp;

    const float4 sv = ((const float4*)state)[(size_t)b * 32 + lane];
    const float4 uv = ((const float4*)U)[(size_t)b * 32 + lane];
    float4 sl[NSLOT];
    {
        const float4* slp = (const float4*)slots + (size_t)b * 256;
#pragma unroll
        for (int n = 0; n < NSLOT; n++) sl[n] = slp[n * 32 + lane];
    }
    const float4 aa = ((const float4*)acts)[(size_t)b * 2];
    const float4 ab = ((const float4*)acts)[(size_t)b * 2 + 1];
    const float4 wg0 = ((const float4*)Wg_w)[lane];
    const float4 wg1 = ((const float4*)Wg_w)[32 + lane];

    float a_[NSLOT] = {aa.x, aa.y, aa.z, aa.w, ab.x, ab.y, ab.z, ab.w};
    float na[NSLOT];
#pragma unroll
    for (int n = 0; n < NSLOT; n++) na[n] = a_[n] * 0.95f;

    float4 wm4 = make_float4(0.f, 0.f, 0.f, 0.f);
#pragma unroll
    for (int n = 0; n < NSLOT; n++) {
        wm4.x = fmaf(na[n], sl[n].x, wm4.x);
        wm4.y = fmaf(na[n], sl[n].y, wm4.y);
        wm4.z = fmaf(na[n], sl[n].z, wm4.z);
        wm4.w = fmaf(na[n], sl[n].w, wm4.w);
    }
    float gdp = fmaf(0.125f, dot4(wm4, wg1), dot4(sv, wg0));
    float sn2 = dot4(sv, sv);
    float du[NSLOT], ds[NSLOT], qn[NSLOT];
#pragma unroll
    for (int n = 0; n < NSLOT; n++) {
        du[n] = dot4(uv, sl[n]);
        ds[n] = dot4(sv, sl[n]);
        qn[n] = dot4(sl[n], sl[n]);
    }

#pragma unroll
    for (int o = 16; o; o >>= 1) {
#pragma unroll
        for (int n = 0; n < NSLOT; n++) {
            du[n] += __shfl_xor_sync(0xFFFFFFFFu, du[n], o);
            ds[n] += __shfl_xor_sync(0xFFFFFFFFu, ds[n], o);
            qn[n] += __shfl_xor_sync(0xFFFFFFFFu, qn[n], o);
        }
        sn2 += __shfl_xor_sync(0xFFFFFFFFu, sn2, o);
        gdp += __shfl_xor_sync(0xFFFFFFFFu, gdp, o);
    }

    const float gd = gdp + Wg_b[0];
    const float gate = 1.f / (1.f + __expf(-gd));
    const float stn = fmaxf(sqrtf(sn2), 1e-12f);
    const float inv_stn = 1.f / stn;

    const float inv_sqrt_d = 0.08838834764831845f;
    float attn[NSLOT];
    float mx = -INFINITY;
#pragma unroll
    for (int n = 0; n < NSLOT; n++) {
        attn[n] = du[n] * inv_sqrt_d * a_[n];
        mx = fmaxf(mx, attn[n]);
    }
    float se = 0.f;
#pragma unroll
    for (int n = 0; n < NSLOT; n++) {
        attn[n] = __expf(attn[n] - mx);
        se += attn[n];
    }
    const float inv_se = 1.f / se;

    float simmax = -INFINITY;
#pragma unroll
    for (int n = 0; n < NSLOT; n++) {
        float m = (na[n] > 0.01f) ? 1.f : 0.f;
        float c = ds[n] * inv_stn / fmaxf(sqrtf(qn[n]), 1e-12f);
        simmax = fmaxf(simmax, c * m);
    }
    const float novelty = 1.f - fminf(fmaxf(simmax, 0.f), 1.f);
    const bool do_write = (novelty > 0.3f) || (gate > 0.5f);

    int weakest = 0;
    float mn = na[0];
#pragma unroll
    for (int n = 1; n < NSLOT; n++)
        if (na[n] < mn) { mn = na[n]; weakest = n; }
    const int sel = do_write ? weakest : -1;

    float swv[NSLOT];
    float swmx = -INFINITY;
#pragma unroll
    for (int n = 0; n < NSLOT; n++) {
        swv[n] = (n == sel) ? 1.f : na[n];
        swmx = fmaxf(swmx, swv[n]);
    }
    float ssum = 0.f;
#pragma unroll
    for (int n = 0; n < NSLOT; n++) {
        swv[n] = __expf(swv[n] - swmx);
        ssum += swv[n];
    }
    const float inv_ss = 1.f / ssum;

    float4* orow4 = (float4*)(out + (size_t)b * OUTW);
    float4 ro = make_float4(0.f, 0.f, 0.f, 0.f);
    float4 sm = make_float4(0.f, 0.f, 0.f, 0.f);
#pragma unroll
    for (int n = 0; n < NSLOT; n++) {
        const float wa = attn[n] * inv_se;
        const float ws = swv[n] * inv_ss;
        float4 x = sl[n];
        float4 v = (n == sel) ? sv : x;
        ro.x = fmaf(wa, x.x, ro.x);  ro.y = fmaf(wa, x.y, ro.y);
        ro.z = fmaf(wa, x.z, ro.z);  ro.w = fmaf(wa, x.w, ro.w);
        sm.x = fmaf(ws, v.x, sm.x);  sm.y = fmaf(ws, v.y, sm.y);
        sm.z = fmaf(ws, v.z, sm.z);  sm.w = fmaf(ws, v.w, sm.w);
        orow4[64 + n * 32 + lane] = v;
    }
    orow4[lane] = ro;
    ((float4*)S)[(size_t)b * 32 + lane] = sm;
    if (lane < NSLOT) {
        float v = (lane == sel) ? 1.f : na[lane];
        out[(size_t)b * OUTW + 2 * D + NSLOT * D + lane] = v;
    }
}

// ---------------------------------------------------------------------------
extern "C" void kernel_launch(void* const* d_in, const int* in_sizes, int n_in,
                              void* d_out, int out_size) {
    const float* state = (const float*)d_in[0];
    const float* slots = (const float*)d_in[1];
    const float* acts  = (const float*)d_in[2];
    const float* Wq    = (const float*)d_in[3];
    const float* Wk    = (const float*)d_in[4];
    const float* Wg_w  = (const float*)d_in[5];
    const float* Wg_b  = (const float*)d_in[6];
    const float* Wf    = (const float*)d_in[7];
    float* out = (float*)d_out;

    const int B = in_sizes[0] / D;

    void *pU, *pS, *pBUhi, *pBUlo, *pBFhi, *pBFlo;
    cudaGetSymbolAddress(&pU, g_U);
    cudaGetSymbolAddress(&pS, g_S);
    cudaGetSymbolAddress(&pBUhi, g_BUhi);
    cudaGetSymbolAddress(&pBUlo, g_BUlo);
    cudaGetSymbolAddress(&pBFhi, g_BFhi);
    cudaGetSymbolAddress(&pBFlo, g_BFlo);

    cudaFuncSetAttribute(tc_gemm, cudaFuncAttributeMaxDynamicSharedMemorySize, 65536);

    prep_kernel<<<256, 128>>>(Wq, Wk, Wf);
    tc_gemm<<<B / 128, 256, 65536>>>(state, (const uint2*)pBUhi, (const uint2*)pBUlo,
                                     (float*)pU, D, 0);
    ew_kernel<<<B / 8, 256>>>(state, slots, acts, Wg_w, Wg_b,
                              (const float*)pU, (float*)pS, out);
    tc_gemm<<<B / 128, 256, 65536>>>((const float*)pS, (const uint2*)pBFhi,
                                     (const uint2*)pBFlo, out, OUTW, D);
}

// round 7
// speedup vs baseline: 1.9653x; 1.0736x over previous
#include <cuda_runtime.h>
#include <cuda_bf16.h>
#include <math.h>

#define D 128
#define NSLOT 8
#define BMAX 65536
#define OUTW 1288   // 2*D + NSLOT*D + NSLOT

// scratch (static device globals; no runtime allocation)
__device__ float g_U[(size_t)BMAX * D];   // state @ M
__device__ float g_S[(size_t)BMAX * D];   // softmax-weighted new_slots sum
// B operands in per-lane mma fragment layout (uint2 per lane per 16x8 tile)
__device__ uint2 g_BUhi[D * D / 4], g_BUlo[D * D / 4];   // B[k][n] = M[k][n]
__device__ uint2 g_BFhi[D * D / 4], g_BFlo[D * D / 4];   // B[k][n] = Wf[n][k]

// ---------------------------------------------------------------------------
// helpers
// ---------------------------------------------------------------------------
__device__ __forceinline__ float dot4(float4 a, float4 b) {
    return fmaf(a.x, b.x, fmaf(a.y, b.y, fmaf(a.z, b.z, a.w * b.w)));
}
// pack two f32 -> bf16x2 (x -> low half, y -> high half)
__device__ __forceinline__ unsigned pack_bf(float x, float y) {
    unsigned r;
    asm("cvt.rn.bf16x2.f32 %0, %1, %2;" : "=r"(r) : "f"(y), "f"(x));
    return r;
}
__device__ __forceinline__ float lo_f(unsigned r) { return __uint_as_float(r << 16); }
__device__ __forceinline__ float hi_f(unsigned r) { return __uint_as_float(r & 0xffff0000u); }

__device__ __forceinline__ void mma_bf16(float* c, uint4 a, uint2 b) {
    asm volatile(
        "mma.sync.aligned.m16n8k16.row.col.f32.bf16.bf16.f32 "
        "{%0,%1,%2,%3}, {%4,%5,%6,%7}, {%8,%9}, {%0,%1,%2,%3};"
        : "+f"(c[0]), "+f"(c[1]), "+f"(c[2]), "+f"(c[3])
        : "r"(a.x), "r"(a.y), "r"(a.z), "r"(a.w), "r"(b.x), "r"(b.y));
}

// fragment address math for B (16x8 k×n tile), PTX ISA m16n8k16 ownership:
//   lane = (n%8)*4 + (k%8)/2 ; reg = (k%16)/8 ; half = k%2
__device__ __forceinline__ void store_b_frag(uint2* arr, int k, int n,
                                             unsigned short bits) {
    int lane = ((n & 7) << 2) + ((k & 7) >> 1);
    int fs = ((k >> 4) << 4) + (n >> 3);           // frag-set = ktile*16 + ntile
    int us = (fs * 32 + lane) * 4 + (((k >> 3) & 1) << 1) + (k & 1);
    ((unsigned short*)arr)[us] = bits;
}

// ---------------------------------------------------------------------------
// prep: blocks 0..127 compute M[d][*] = (Wq^T Wk)[d][*] -> g_BU (k=d, n=t)
//       blocks 128..255: Wf rows -> g_BF (B[k][n] = Wf[n][k]: n=blk, k=t)
// ---------------------------------------------------------------------------
__global__ void prep_kernel(const float* __restrict__ Wq,
                            const float* __restrict__ Wk,
                            const float* __restrict__ Wf) {
    int d = blockIdx.x;
    int t = threadIdx.x;
    if (d < D) {
        float a0 = 0.f, a1 = 0.f, a2 = 0.f, a3 = 0.f;
#pragma unroll 8
        for (int e = 0; e < D; e += 4) {
            a0 = fmaf(Wq[(e + 0) * D + d], Wk[(e + 0) * D + t], a0);
            a1 = fmaf(Wq[(e + 1) * D + d], Wk[(e + 1) * D + t], a1);
            a2 = fmaf(Wq[(e + 2) * D + d], Wk[(e + 2) * D + t], a2);
            a3 = fmaf(Wq[(e + 3) * D + d], Wk[(e + 3) * D + t], a3);
        }
        float m = (a0 + a1) + (a2 + a3);
        __nv_bfloat16 hb = __float2bfloat16(m);
        float lo = m - __bfloat162float(hb);
        __nv_bfloat16 lb = __float2bfloat16(lo);
        store_b_frag(g_BUhi, d, t, *(unsigned short*)&hb);
        store_b_frag(g_BUlo, d, t, *(unsigned short*)&lb);
    } else {
        int n = d - D;
        float m = Wf[n * D + t];
        __nv_bfloat16 hb = __float2bfloat16(m);
        float lo = m - __bfloat162float(hb);
        __nv_bfloat16 lb = __float2bfloat16(lo);
        store_b_frag(g_BFhi, t, n, *(unsigned short*)&hb);
        store_b_frag(g_BFlo, t, n, *(unsigned short*)&lb);
    }
}

// ---------------------------------------------------------------------------
// Tensor-core GEMM via mma.sync bf16, 3-term split. v2: no smem, no barrier.
// C[brow+m][coff+n] = sum_k A[brow+m][k] * B[k][n]
// 256 threads, 64x128 tile/CTA. warp(wm 0..3, wn 0..1): mtile wm, 64-col half wn.
// A frags loaded per-lane from global and converted in registers.
// B frags LDG'd from global (64KB, L1-resident).
// ---------------------------------------------------------------------------
__global__ __launch_bounds__(256, 3)
void tc_gemm(const float* __restrict__ A,
             const uint2* __restrict__ Bhi, const uint2* __restrict__ Blo,
             float* __restrict__ C, int ldc, int coff) {
    const int warp = threadIdx.x >> 5;
    const int lane = threadIdx.x & 31;
    const int wm = warp & 3;
    const int wn = warp >> 2;
    const int brow = blockIdx.x * 64 + wm * 16;
    const int r = brow + (lane >> 2);
    const int cb = (lane & 3) << 1;

    float acc[8][4];
#pragma unroll
    for (int j = 0; j < 8; j++)
#pragma unroll
        for (int q = 0; q < 4; q++) acc[j][q] = 0.f;

    const float* ap = A + (size_t)r * D + cb;

#pragma unroll
    for (int kt = 0; kt < 8; kt++) {
        // per-lane A fragment (m16n8k16 row-major A ownership), fp32 -> hi/lo bf16
        const float* p = ap + kt * 16;
        float2 p00 = *(const float2*)p;
        float2 p01 = *(const float2*)(p + 8);
        float2 p10 = *(const float2*)(p + 8 * D);
        float2 p11 = *(const float2*)(p + 8 * D + 8);
        uint4 h, l;
        h.x = pack_bf(p00.x, p00.y);
        h.y = pack_bf(p10.x, p10.y);
        h.z = pack_bf(p01.x, p01.y);
        h.w = pack_bf(p11.x, p11.y);
        l.x = pack_bf(p00.x - lo_f(h.x), p00.y - hi_f(h.x));
        l.y = pack_bf(p10.x - lo_f(h.y), p10.y - hi_f(h.y));
        l.z = pack_bf(p01.x - lo_f(h.z), p01.y - hi_f(h.z));
        l.w = pack_bf(p11.x - lo_f(h.w), p11.y - hi_f(h.w));

#pragma unroll
        for (int nt = 0; nt < 8; nt++) {
            int fs = kt * 16 + wn * 8 + nt;
            uint2 bh = Bhi[fs * 32 + lane];
            uint2 bl = Blo[fs * 32 + lane];
            mma_bf16(acc[nt], h, bh);
            mma_bf16(acc[nt], h, bl);
            mma_bf16(acc[nt], l, bh);
        }
    }

    // epilogue: c0,c1 -> (row, col..col+1); c2,c3 -> (row+8, ...)
    const int row = brow + (lane >> 2);
#pragma unroll
    for (int nt = 0; nt < 8; nt++) {
        const int col = coff + wn * 64 + nt * 8 + cb;
        float* cp = C + (size_t)row * ldc + col;
        *(float2*)cp = make_float2(acc[nt][0], acc[nt][1]);
        *(float2*)(cp + 8 * ldc) = make_float2(acc[nt][2], acc[nt][3]);
    }
}

// ---------------------------------------------------------------------------
// Elementwise kernel v3 + streaming cache hints on zero-reuse traffic
// ---------------------------------------------------------------------------
__global__ __launch_bounds__(256)
void ew_kernel(const float* __restrict__ state, const float* __restrict__ slots,
               const float* __restrict__ acts, const float* __restrict__ Wg_w,
               const float* __restrict__ Wg_b, const float* __restrict__ U,
               float* __restrict__ S, float* __restrict__ out) {
    const int warp = threadIdx.x >> 5;
    const int lane = threadIdx.x & 31;
    const int b = blockIdx.x * 8 + warp;

    const float4 sv = ((const float4*)state)[(size_t)b * 32 + lane];
    const float4 uv = ((const float4*)U)[(size_t)b * 32 + lane];
    float4 sl[NSLOT];
    {
        const float4* slp = (const float4*)slots + (size_t)b * 256;
#pragma unroll
        for (int n = 0; n < NSLOT; n++) sl[n] = __ldcs(slp + n * 32 + lane);
    }
    const float4 aa = ((const float4*)acts)[(size_t)b * 2];
    const float4 ab = ((const float4*)acts)[(size_t)b * 2 + 1];
    const float4 wg0 = ((const float4*)Wg_w)[lane];
    const float4 wg1 = ((const float4*)Wg_w)[32 + lane];

    float a_[NSLOT] = {aa.x, aa.y, aa.z, aa.w, ab.x, ab.y, ab.z, ab.w};
    float na[NSLOT];
#pragma unroll
    for (int n = 0; n < NSLOT; n++) na[n] = a_[n] * 0.95f;

    float4 wm4 = make_float4(0.f, 0.f, 0.f, 0.f);
#pragma unroll
    for (int n = 0; n < NSLOT; n++) {
        wm4.x = fmaf(na[n], sl[n].x, wm4.x);
        wm4.y = fmaf(na[n], sl[n].y, wm4.y);
        wm4.z = fmaf(na[n], sl[n].z, wm4.z);
        wm4.w = fmaf(na[n], sl[n].w, wm4.w);
    }
    float gdp = fmaf(0.125f, dot4(wm4, wg1), dot4(sv, wg0));
    float sn2 = dot4(sv, sv);
    float du[NSLOT], ds[NSLOT], qn[NSLOT];
#pragma unroll
    for (int n = 0; n < NSLOT; n++) {
        du[n] = dot4(uv, sl[n]);
        ds[n] = dot4(sv, sl[n]);
        qn[n] = dot4(sl[n], sl[n]);
    }

#pragma unroll
    for (int o = 16; o; o >>= 1) {
#pragma unroll
        for (int n = 0; n < NSLOT; n++) {
            du[n] += __shfl_xor_sync(0xFFFFFFFFu, du[n], o);
            ds[n] += __shfl_xor_sync(0xFFFFFFFFu, ds[n], o);
            qn[n] += __shfl_xor_sync(0xFFFFFFFFu, qn[n], o);
        }
        sn2 += __shfl_xor_sync(0xFFFFFFFFu, sn2, o);
        gdp += __shfl_xor_sync(0xFFFFFFFFu, gdp, o);
    }

    const float gd = gdp + Wg_b[0];
    const float gate = 1.f / (1.f + __expf(-gd));
    const float stn = fmaxf(sqrtf(sn2), 1e-12f);
    const float inv_stn = 1.f / stn;

    const float inv_sqrt_d = 0.08838834764831845f;
    float attn[NSLOT];
    float mx = -INFINITY;
#pragma unroll
    for (int n = 0; n < NSLOT; n++) {
        attn[n] = du[n] * inv_sqrt_d * a_[n];
        mx = fmaxf(mx, attn[n]);
    }
    float se = 0.f;
#pragma unroll
    for (int n = 0; n < NSLOT; n++) {
        attn[n] = __expf(attn[n] - mx);
        se += attn[n];
    }
    const float inv_se = 1.f / se;

    float simmax = -INFINITY;
#pragma unroll
    for (int n = 0; n < NSLOT; n++) {
        float m = (na[n] > 0.01f) ? 1.f : 0.f;
        float c = ds[n] * inv_stn / fmaxf(sqrtf(qn[n]), 1e-12f);
        simmax = fmaxf(simmax, c * m);
    }
    const float novelty = 1.f - fminf(fmaxf(simmax, 0.f), 1.f);
    const bool do_write = (novelty > 0.3f) || (gate > 0.5f);

    int weakest = 0;
    float mn = na[0];
#pragma unroll
    for (int n = 1; n < NSLOT; n++)
        if (na[n] < mn) { mn = na[n]; weakest = n; }
    const int sel = do_write ? weakest : -1;

    float swv[NSLOT];
    float swmx = -INFINITY;
#pragma unroll
    for (int n = 0; n < NSLOT; n++) {
        swv[n] = (n == sel) ? 1.f : na[n];
        swmx = fmaxf(swmx, swv[n]);
    }
    float ssum = 0.f;
#pragma unroll
    for (int n = 0; n < NSLOT; n++) {
        swv[n] = __expf(swv[n] - swmx);
        ssum += swv[n];
    }
    const float inv_ss = 1.f / ssum;

    float4* orow4 = (float4*)(out + (size_t)b * OUTW);
    float4 ro = make_float4(0.f, 0.f, 0.f, 0.f);
    float4 sm = make_float4(0.f, 0.f, 0.f, 0.f);
#pragma unroll
    for (int n = 0; n < NSLOT; n++) {
        const float wa = attn[n] * inv_se;
        const float ws = swv[n] * inv_ss;
        float4 x = sl[n];
        float4 v = (n == sel) ? sv : x;
        ro.x = fmaf(wa, x.x, ro.x);  ro.y = fmaf(wa, x.y, ro.y);
        ro.z = fmaf(wa, x.z, ro.z);  ro.w = fmaf(wa, x.w, ro.w);
        sm.x = fmaf(ws, v.x, sm.x);  sm.y = fmaf(ws, v.y, sm.y);
        sm.z = fmaf(ws, v.z, sm.z);  sm.w = fmaf(ws, v.w, sm.w);
        __stcs(orow4 + 64 + n * 32 + lane, v);
    }
    __stcs(orow4 + lane, ro);
    ((float4*)S)[(size_t)b * 32 + lane] = sm;
    if (lane < NSLOT) {
        float v = (lane == sel) ? 1.f : na[lane];
        out[(size_t)b * OUTW + 2 * D + NSLOT * D + lane] = v;
    }
}

// ---------------------------------------------------------------------------
extern "C" void kernel_launch(void* const* d_in, const int* in_sizes, int n_in,
                              void* d_out, int out_size) {
    const float* state = (const float*)d_in[0];
    const float* slots = (const float*)d_in[1];
    const float* acts  = (const float*)d_in[2];
    const float* Wq    = (const float*)d_in[3];
    const float* Wk    = (const float*)d_in[4];
    const float* Wg_w  = (const float*)d_in[5];
    const float* Wg_b  = (const float*)d_in[6];
    const float* Wf    = (const float*)d_in[7];
    float* out = (float*)d_out;

    const int B = in_sizes[0] / D;

    void *pU, *pS, *pBUhi, *pBUlo, *pBFhi, *pBFlo;
    cudaGetSymbolAddress(&pU, g_U);
    cudaGetSymbolAddress(&pS, g_S);
    cudaGetSymbolAddress(&pBUhi, g_BUhi);
    cudaGetSymbolAddress(&pBUlo, g_BUlo);
    cudaGetSymbolAddress(&pBFhi, g_BFhi);
    cudaGetSymbolAddress(&pBFlo, g_BFlo);

    prep_kernel<<<256, 128>>>(Wq, Wk, Wf);
    tc_gemm<<<B / 64, 256>>>(state, (const uint2*)pBUhi, (const uint2*)pBUlo,
                             (float*)pU, D, 0);
    ew_kernel<<<B / 8, 256>>>(state, slots, acts, Wg_w, Wg_b,
                              (const float*)pU, (float*)pS, out);
    tc_gemm<<<B / 64, 256>>>((const float*)pS, (const uint2*)pBFhi,
                             (const uint2*)pBFlo, out, OUTW, D);
}